// round 13
// baseline (speedup 1.0000x reference)
#include <cuda_runtime.h>
#include <cuda.h>
#include <cuda_bf16.h>
#include <cstdint>
#include <cstddef>

#define NROWS 32768
#define KDIM  4096
#define RDIM  256
#define NTILE 16          // KDIM / 256 n-tiles per row
#define CAND_CAP 32       // candidate slots per (row, n-tile)

// ---------------- static device scratch (no allocs allowed) ----------------
__device__ __nv_bfloat16 g_Asp[(size_t)NROWS * 512];   // H split hi/lo, 32MB
__device__ __nv_bfloat16 g_Bsp[(size_t)KDIM * 512];    // Qt split hi/lo, 4MB
__device__ float  g_statsM[(size_t)NROWS * NTILE];                // tile max, 2MB
__device__ int    g_ccnt  [(size_t)NROWS * NTILE];                // 2MB
__device__ float2 g_cand  [(size_t)NROWS * NTILE * CAND_CAP];     // (val, idx-bits), 128MB

// =========================================================================================
// PTX helpers
// =========================================================================================
__device__ __forceinline__ uint32_t smem_u32(const void* p) {
    uint32_t a;
    asm("{ .reg .u64 t; cvta.to.shared.u64 t, %1; cvt.u32.u64 %0, t; }" : "=r"(a) : "l"(p));
    return a;
}

#define MBARRIER_INIT(addr, cnt) \
    asm volatile("mbarrier.init.shared.b64 [%0], %1;" :: "r"((uint32_t)(addr)), "r"((uint32_t)(cnt)) : "memory")

#define MBARRIER_EXPECT_TX(addr, bytes) \
    asm volatile("mbarrier.arrive.expect_tx.shared.b64 _, [%0], %1;" :: "r"((uint32_t)(addr)), "r"((uint32_t)(bytes)) : "memory")

#define MBARRIER_WAIT_PARITY(addr, ph) do {                                             \
    uint32_t _m = (uint32_t)(addr); uint32_t _p = (uint32_t)(ph); uint32_t _d;          \
    asm volatile("{ .reg .pred p; mbarrier.try_wait.parity.acquire.cta.shared::cta.b64 p, [%1], %2; selp.b32 %0, 1, 0, p; }" \
                 : "=r"(_d) : "r"(_m), "r"(_p) : "memory");                             \
    if (!_d) {                                                                          \
        asm volatile("{ .reg .pred P1; WL_%=: mbarrier.try_wait.parity.acquire.cta.shared::cta.b64 P1, [%0], %1, 0x989680; " \
                     "@P1 bra.uni WD_%=; bra.uni WL_%=; WD_%=: }"                       \
                     :: "r"(_m), "r"(_p) : "memory");                                   \
    }                                                                                   \
} while (0)

__device__ __forceinline__ void tma2d(uint32_t dst, const CUtensorMap* m, int x, int y, uint32_t mbar) {
    asm volatile("cp.async.bulk.tensor.2d.shared::cta.global.tile.mbarrier::complete_tx::bytes "
                 "[%0], [%1, {%2, %3}], [%4];"
                 :: "r"(dst), "l"(m), "r"(x), "r"(y), "r"(mbar) : "memory");
}

static constexpr uint64_t SMEM_DESC_BASE_SW128 =
    (uint64_t(2) << 61) | (uint64_t(1) << 46) | (uint64_t(64) << 32) | (uint64_t(1) << 16);
#define MAKE_SMEM_DESC(a) (SMEM_DESC_BASE_SW128 | ((uint64_t)((a) >> 4) & 0x3FFF))

#define LDTM32(r, addr) \
    asm volatile( \
        "tcgen05.ld.sync.aligned.32x32b.x32.b32 " \
        "{%0, %1, %2, %3, %4, %5, %6, %7, %8, %9, %10, %11, %12, %13, %14, %15, " \
        " %16, %17, %18, %19, %20, %21, %22, %23, %24, %25, %26, %27, %28, %29, %30, %31}, [%32];" \
        : "=r"((r)[0]),  "=r"((r)[1]),  "=r"((r)[2]),  "=r"((r)[3]), \
          "=r"((r)[4]),  "=r"((r)[5]),  "=r"((r)[6]),  "=r"((r)[7]), \
          "=r"((r)[8]),  "=r"((r)[9]),  "=r"((r)[10]), "=r"((r)[11]), \
          "=r"((r)[12]), "=r"((r)[13]), "=r"((r)[14]), "=r"((r)[15]), \
          "=r"((r)[16]), "=r"((r)[17]), "=r"((r)[18]), "=r"((r)[19]), \
          "=r"((r)[20]), "=r"((r)[21]), "=r"((r)[22]), "=r"((r)[23]), \
          "=r"((r)[24]), "=r"((r)[25]), "=r"((r)[26]), "=r"((r)[27]), \
          "=r"((r)[28]), "=r"((r)[29]), "=r"((r)[30]), "=r"((r)[31]) \
        : "r"(addr))

// =========================================================================================
// tcgen05 GEMM 256x256 tile (R8-validated mainloop) + LIGHT stats epilogue:
//   pass 1: tile max m_t (fmax only); pass 2: threshold-collect candidates (v > m_t - 95).
// NO exp, NO logits store. Entries below m_t-95 are exact zeros in fp32 softmax.
// =========================================================================================
#define GM_STAGES 3
#define GM_NKB    12
#define GM_ABYTES 32768
#define GM_BBYTES 32768
#define SM_OFF_TMEM     0
#define SM_OFF_FULL(s)  (8 + (s) * 8)
#define SM_OFF_MDONE(s) (40 + (s) * 8)
#define SM_OFF_FINAL    72
#define SM_OFF_A(s)     (1024 + (s) * GM_ABYTES)
#define SM_OFF_B(s)     (1024 + 3 * GM_ABYTES + (s) * GM_BBYTES)
#define GM_SMEM_TOTAL   (1024 + 6 * 32768)   // 197632

#define GM_IDESC ((1u << 4) | (1u << 7) | (1u << 10) | ((256u / 8) << 17) | ((128u / 16) << 24))

__global__ __launch_bounds__(128) void gemm_tc(const __grid_constant__ CUtensorMap tmA,
                                               const __grid_constant__ CUtensorMap tmB) {
#if defined(__CUDA_ARCH_FEAT_SM103_ALL) || defined(__CUDA_ARCH_FEAT_SM100_ALL)
    extern __shared__ char smem[];
    const uint32_t sb = smem_u32(smem);
    const int tid = threadIdx.x;
    const int wid = tid >> 5;
    const int lid = tid & 31;
    const int m0 = blockIdx.y * 256;
    const int n0 = blockIdx.x * 256;

    if (wid == 0)
        asm volatile("tcgen05.alloc.cta_group::1.sync.aligned.shared::cta.b32 [%0], %1;"
                     :: "r"(sb + SM_OFF_TMEM), "r"(512u) : "memory");
    if (tid == 0) {
        for (int s = 0; s < GM_STAGES; s++) {
            MBARRIER_INIT(sb + SM_OFF_FULL(s), 1);
            MBARRIER_INIT(sb + SM_OFF_MDONE(s), 1);
        }
        MBARRIER_INIT(sb + SM_OFF_FINAL, 1);
    }
    __syncthreads();

    uint32_t tmem;
    asm volatile("ld.shared.b32 %0, [%1];" : "=r"(tmem) : "r"(sb + SM_OFF_TMEM));

    if (tid == 0) {
        int phase[GM_STAGES] = {0, 0, 0};
#pragma unroll 1
        for (int i = 0; i < GM_NKB; i++) {
            int s = i % GM_STAGES;
            if (i >= GM_STAGES) {
                MBARRIER_WAIT_PARITY(sb + SM_OFF_MDONE(s), phase[s]);
                phase[s] ^= 1;
            }
            MBARRIER_EXPECT_TX(sb + SM_OFF_FULL(s), GM_ABYTES + GM_BBYTES);
            int kk = (i & 3) * 64;
            int a_k = (i < 8) ? kk : 256 + kk;                       // hi,hi,lo
            int b_k = (i < 4) ? kk : ((i < 8) ? 256 + kk : kk);      // hi,lo,hi
            tma2d(sb + SM_OFF_A(s), &tmA, a_k, m0, sb + SM_OFF_FULL(s));
            tma2d(sb + SM_OFF_B(s), &tmB, b_k, n0, sb + SM_OFF_FULL(s));
        }
    } else if (tid == 32) {
        int phase[GM_STAGES] = {0, 0, 0};
#pragma unroll 1
        for (int i = 0; i < GM_NKB; i++) {
            int s = i % GM_STAGES;
            MBARRIER_WAIT_PARITY(sb + SM_OFF_FULL(s), phase[s]);
            phase[s] ^= 1;
            uint64_t ad0 = MAKE_SMEM_DESC(sb + SM_OFF_A(s));
            uint64_t ad1 = MAKE_SMEM_DESC(sb + SM_OFF_A(s) + 16384);
            uint64_t bd  = MAKE_SMEM_DESC(sb + SM_OFF_B(s));
#pragma unroll
            for (int k = 0; k < 4; k++) {
                uint32_t en = (i > 0 || k > 0) ? 1u : 0u;
                asm volatile(
                    "{ .reg .pred p; setp.ne.u32 p, %4, 0;"
                    "tcgen05.mma.cta_group::1.kind::f16 [%0], %1, %2, %3, {%5, %5, %5, %5}, p; }"
                    :: "r"(tmem), "l"(ad0 + k * 2), "l"(bd + k * 2), "r"(GM_IDESC),
                       "r"(en), "r"(0u) : "memory");
                asm volatile(
                    "{ .reg .pred p; setp.ne.u32 p, %4, 0;"
                    "tcgen05.mma.cta_group::1.kind::f16 [%0], %1, %2, %3, {%5, %5, %5, %5}, p; }"
                    :: "r"(tmem + 256), "l"(ad1 + k * 2), "l"(bd + k * 2), "r"(GM_IDESC),
                       "r"(en), "r"(0u) : "memory");
            }
            asm volatile("tcgen05.commit.cta_group::1.mbarrier::arrive::one.shared::cluster.b64 [%0];"
                         :: "r"(sb + SM_OFF_MDONE(s)) : "memory");
        }
        asm volatile("tcgen05.commit.cta_group::1.mbarrier::arrive::one.shared::cluster.b64 [%0];"
                     :: "r"(sb + SM_OFF_FINAL) : "memory");
    }

    MBARRIER_WAIT_PARITY(sb + SM_OFF_FINAL, 0);
    asm volatile("tcgen05.fence::after_thread_sync;" ::: "memory");

    // ---- light stats epilogue: max + threshold-collect (no exp) ----
#pragma unroll 1
    for (int slab = 0; slab < 2; slab++) {
        const int row = m0 + slab * 128 + wid * 32 + lid;
        const uint32_t tbase = tmem + slab * 256;
        const size_t sbase = (size_t)row * NTILE + blockIdx.x;

        float mt = -3.4e38f;
#pragma unroll 1
        for (int c = 0; c < 8; c++) {
            uint32_t r[32];
            LDTM32(r, tbase + c * 32);
            asm volatile("tcgen05.wait::ld.sync.aligned;" ::: "memory");
#pragma unroll
            for (int j = 0; j < 32; j++) mt = fmaxf(mt, __uint_as_float(r[j]));
        }

        const float thr = mt - 95.0f;
        int cnt = 0;
        float2* cdst = g_cand + sbase * CAND_CAP;
#pragma unroll 1
        for (int c = 0; c < 8; c++) {
            uint32_t r[32];
            LDTM32(r, tbase + c * 32);
            asm volatile("tcgen05.wait::ld.sync.aligned;" ::: "memory");
#pragma unroll
            for (int j = 0; j < 32; j++) {
                float v = __uint_as_float(r[j]);
                if (v > thr) {                        // rare (~3 per tile)
                    if (cnt < CAND_CAP)
                        cdst[cnt] = make_float2(v, __int_as_float(n0 + c * 32 + j));
                    cnt++;
                }
            }
        }
        g_statsM[sbase] = mt;
        g_ccnt[sbase] = min(cnt, CAND_CAP);
    }
    asm volatile("tcgen05.fence::before_thread_sync;" ::: "memory");
    __syncthreads();
    if (wid == 0) {
        asm volatile("tcgen05.relinquish_alloc_permit.cta_group::1.sync.aligned;");
        asm volatile("tcgen05.dealloc.cta_group::1.sync.aligned.b32 %0, %1;" :: "r"(tmem), "r"(512u));
    }
#endif  // arch guard
}

// =========================================================================================
// Fused prologue (R9-validated): y<32 -> Qt GEMM tile w/ split epilogue; y>=32 -> H split
// =========================================================================================
__device__ __forceinline__ unsigned long long pk2(float lo, float hi) {
    unsigned long long r;
    asm("mov.b64 %0, {%1, %2};" : "=l"(r) : "r"(__float_as_uint(lo)), "r"(__float_as_uint(hi)));
    return r;
}
__device__ __forceinline__ void fma2(unsigned long long &d, unsigned long long a, unsigned long long b) {
    asm("fma.rn.f32x2 %0, %1, %2, %3;" : "=l"(d) : "l"(a), "l"(b), "l"(d));
}
__device__ __forceinline__ float2 upk(unsigned long long v) {
    unsigned lo, hi;
    asm("mov.b64 {%0, %1}, %2;" : "=r"(lo), "=r"(hi) : "l"(v));
    float2 f; f.x = __uint_as_float(lo); f.y = __uint_as_float(hi);
    return f;
}

#define SPLIT_YBASE 32

__global__ __launch_bounds__(256) void prologue_kernel(const float* __restrict__ H,
                                                       const float* __restrict__ Lmat,
                                                       const float* __restrict__ W,
                                                       __nv_bfloat16* __restrict__ Asp,
                                                       __nv_bfloat16* __restrict__ Bsp) {
    __shared__ float As[32][132];
    __shared__ float Bs[32][132];
    const int tid = threadIdx.x;

    if (blockIdx.y >= SPLIT_YBASE) {
        int sbid = (blockIdx.y - SPLIT_YBASE) * 2 + blockIdx.x;
        int f = sbid * 256 + tid;
        int m = f >> 6;
        int r = (f & 63) << 2;
        float4 x = ((const float4*)H)[f];
        __nv_bfloat16 h0 = __float2bfloat16(x.x), h1 = __float2bfloat16(x.y);
        __nv_bfloat16 h2 = __float2bfloat16(x.z), h3 = __float2bfloat16(x.w);
        __nv_bfloat162 hiA(h0, h1), hiB(h2, h3);
        __nv_bfloat162 loA(__float2bfloat16(x.x - __bfloat162float(h0)),
                           __float2bfloat16(x.y - __bfloat162float(h1)));
        __nv_bfloat162 loB(__float2bfloat16(x.z - __bfloat162float(h2)),
                           __float2bfloat16(x.w - __bfloat162float(h3)));
        __nv_bfloat162* dh = (__nv_bfloat162*)(Asp + (size_t)m * 512 + r);
        __nv_bfloat162* dl = (__nv_bfloat162*)(Asp + (size_t)m * 512 + 256 + r);
        dh[0] = hiA; dh[1] = hiB;
        dl[0] = loA; dl[1] = loB;
        return;
    }

    const int K = RDIM;
    const int tx = tid & 15;
    const int ty = tid >> 4;
    const int bm = blockIdx.y * 128;
    const int bn = blockIdx.x * 128;
    const int lrow = tid >> 3;
    const int lcol = (tid & 7) << 2;

    unsigned long long acc[8][4];
#pragma unroll
    for (int i = 0; i < 8; i++)
#pragma unroll
        for (int j = 0; j < 4; j++) acc[i][j] = 0ull;

    for (int kk = 0; kk < K; kk += 32) {
#pragma unroll
        for (int p = 0; p < 4; p++) {
            int r = lrow + p * 32;
            float4 av = *(const float4*)(Lmat + (size_t)(bm + r) * K + kk + lcol);
            As[lcol + 0][r] = av.x; As[lcol + 1][r] = av.y;
            As[lcol + 2][r] = av.z; As[lcol + 3][r] = av.w;
            float4 bv = *(const float4*)(W + (size_t)(bn + r) * K + kk + lcol);
            Bs[lcol + 0][r] = bv.x; Bs[lcol + 1][r] = bv.y;
            Bs[lcol + 2][r] = bv.z; Bs[lcol + 3][r] = bv.w;
        }
        __syncthreads();
#pragma unroll
        for (int k2 = 0; k2 < 32; k2++) {
            float4 a0 = *(const float4*)&As[k2][ty * 8];
            float4 a1 = *(const float4*)&As[k2][ty * 8 + 4];
            float4 b0 = *(const float4*)&Bs[k2][tx * 8];
            float4 b1 = *(const float4*)&Bs[k2][tx * 8 + 4];
            unsigned long long av[8];
            av[0] = pk2(a0.x, a0.x); av[1] = pk2(a0.y, a0.y);
            av[2] = pk2(a0.z, a0.z); av[3] = pk2(a0.w, a0.w);
            av[4] = pk2(a1.x, a1.x); av[5] = pk2(a1.y, a1.y);
            av[6] = pk2(a1.z, a1.z); av[7] = pk2(a1.w, a1.w);
            unsigned long long bv2[4];
            bv2[0] = pk2(b0.x, b0.y); bv2[1] = pk2(b0.z, b0.w);
            bv2[2] = pk2(b1.x, b1.y); bv2[3] = pk2(b1.z, b1.w);
#pragma unroll
            for (int i = 0; i < 8; i++)
#pragma unroll
                for (int j = 0; j < 4; j++) fma2(acc[i][j], av[i], bv2[j]);
        }
        __syncthreads();
    }

#pragma unroll
    for (int i = 0; i < 8; i++) {
        float2 c0 = upk(acc[i][0]), c1 = upk(acc[i][1]);
        float2 c2 = upk(acc[i][2]), c3 = upk(acc[i][3]);
        float v[8] = {c0.x, c0.y, c1.x, c1.y, c2.x, c2.y, c3.x, c3.y};
        int krow = bm + ty * 8 + i;
        int cbase = bn + tx * 8;
        __nv_bfloat162 hi[4], lo[4];
#pragma unroll
        for (int j = 0; j < 4; j++) {
            __nv_bfloat16 h0 = __float2bfloat16(v[2 * j]);
            __nv_bfloat16 h1 = __float2bfloat16(v[2 * j + 1]);
            hi[j] = __nv_bfloat162(h0, h1);
            lo[j] = __nv_bfloat162(__float2bfloat16(v[2 * j] - __bfloat162float(h0)),
                                   __float2bfloat16(v[2 * j + 1] - __bfloat162float(h1)));
        }
        __nv_bfloat162* dh = (__nv_bfloat162*)(Bsp + (size_t)krow * 512 + cbase);
        __nv_bfloat162* dl = (__nv_bfloat162*)(Bsp + (size_t)krow * 512 + 256 + cbase);
#pragma unroll
        for (int j = 0; j < 4; j++) { dh[j] = hi[j]; dl[j] = lo[j]; }
    }
}

// =========================================================================================
// finalize: 1 block per row. M = max of tile maxes; S = sum of exp over candidates only
// (non-candidates contribute < 1e-40 — exact fp32 zero territory). Writes the FULL A row
// (zeros + scattered nonzeros) from registers — replaces the zero-fill kernel — plus C row.
// =========================================================================================
__global__ __launch_bounds__(256) void finalize_kernel(const float* __restrict__ Lmat,
                                                       float* __restrict__ Cout,
                                                       float* __restrict__ Aout) {
    const int n = blockIdx.x;
    const int t = threadIdx.x;
    const size_t base = (size_t)n * NTILE;
    __shared__ float sM, sSum;
    __shared__ int   s_cnt;
    __shared__ int   sk[NTILE * CAND_CAP];
    __shared__ float se[NTILE * CAND_CAP];

    if (t == 0) { sSum = 0.0f; s_cnt = 0; }
    if (t < 32) {
        float m = (t < NTILE) ? g_statsM[base + t] : -3.4e38f;
#pragma unroll
        for (int o = 16; o > 0; o >>= 1) m = fmaxf(m, __shfl_xor_sync(0xffffffffu, m, o));
        if (t == 0) sM = m;
    }
    __syncthreads();
    const float M = sM;

    // gather candidates: NTILE*CAND_CAP = 512 slots, 2 per thread
    for (int sl = t; sl < NTILE * CAND_CAP; sl += 256) {
        int tile = sl / CAND_CAP, slot = sl % CAND_CAP;
        if (slot < g_ccnt[base + tile]) {
            float2 cv = g_cand[(base + tile) * CAND_CAP + slot];
            float e = __expf(cv.x - M);
            if (e > 0.0f) {
                int p = atomicAdd(&s_cnt, 1);
                sk[p] = __float_as_int(cv.y);
                se[p] = e;
                atomicAdd(&sSum, e);
            }
        }
    }
    __syncthreads();
    const float invS = 1.0f / sSum;
    const int c_n = s_cnt;

    // A row: thread owns 16 consecutive floats; zeros + scattered candidates
    {
        float buf[16];
#pragma unroll
        for (int j = 0; j < 16; j++) buf[j] = 0.0f;
        const int kbase = t * 16;
        for (int j = 0; j < c_n; j++) {
            int k = sk[j] - kbase;
            if ((unsigned)k < 16u) buf[k] = se[j] * invS;
        }
        float4* dst = (float4*)(Aout + (size_t)n * KDIM + kbase);
#pragma unroll
        for (int j = 0; j < 4; j++)
            dst[j] = make_float4(buf[4 * j], buf[4 * j + 1], buf[4 * j + 2], buf[4 * j + 3]);
    }

    // C row: thread t owns r = t
    float c = 0.0f;
    for (int j = 0; j < c_n; j++)
        c += se[j] * Lmat[(size_t)sk[j] * RDIM + t];
    Cout[(size_t)n * RDIM + t] = c * invS;
}

// =========================================================================================
// host
// =========================================================================================
typedef CUresult (*PFN_encodeTiled)(CUtensorMap*, CUtensorMapDataType, cuuint32_t, void*,
                                    const cuuint64_t*, const cuuint64_t*, const cuuint32_t*,
                                    const cuuint32_t*, CUtensorMapInterleave, CUtensorMapSwizzle,
                                    CUtensorMapL2promotion, CUtensorMapFloatOOBfill);

static void encode_map(PFN_encodeTiled enc, CUtensorMap* tm, void* ptr,
                       uint64_t rows, uint32_t box_rows) {
    cuuint64_t dims[2]    = {512, rows};
    cuuint64_t strides[1] = {512 * sizeof(__nv_bfloat16)};
    cuuint32_t box[2]     = {64, box_rows};
    cuuint32_t es[2]      = {1, 1};
    enc(tm, CU_TENSOR_MAP_DATA_TYPE_BFLOAT16, 2, ptr, dims, strides, box, es,
        CU_TENSOR_MAP_INTERLEAVE_NONE, CU_TENSOR_MAP_SWIZZLE_128B,
        CU_TENSOR_MAP_L2_PROMOTION_L2_128B, CU_TENSOR_MAP_FLOAT_OOB_FILL_NONE);
}

extern "C" void kernel_launch(void* const* d_in, const int* in_sizes, int n_in,
                              void* d_out, int out_size) {
    (void)in_sizes; (void)n_in; (void)out_size;
    const float* H  = (const float*)d_in[0];   // 32768 x 256
    const float* Lm = (const float*)d_in[1];   // 4096 x 256
    const float* W  = (const float*)d_in[2];   // 256 x 256
    float* Cout = (float*)d_out;
    float* Aout = Cout + (size_t)NROWS * RDIM;

    __nv_bfloat16* Asp; __nv_bfloat16* Bsp;
    cudaGetSymbolAddress((void**)&Asp, g_Asp);
    cudaGetSymbolAddress((void**)&Bsp, g_Bsp);

    static PFN_encodeTiled enc = nullptr;
    if (!enc) {
        void* fn = nullptr;
        cudaDriverEntryPointQueryResult qr;
        cudaGetDriverEntryPoint("cuTensorMapEncodeTiled", &fn, cudaEnableDefault, &qr);
        enc = (PFN_encodeTiled)fn;
    }

    CUtensorMap tmA, tmB;
    encode_map(enc, &tmA, Asp, NROWS, 256);
    encode_map(enc, &tmB, Bsp, KDIM, 256);

    static bool attr_set = false;
    if (!attr_set) {
        cudaFuncSetAttribute(gemm_tc, cudaFuncAttributeMaxDynamicSharedMemorySize, GM_SMEM_TOTAL);
        attr_set = true;
    }

    // 1) fused prologue
    prologue_kernel<<<dim3(2, SPLIT_YBASE + 4096), 256>>>(H, Lm, W, Asp, Bsp);
    // 2) gemm with light stats epilogue (no logits round-trip, no exp)
    gemm_tc<<<dim3(KDIM / 256, NROWS / 256), 128, GM_SMEM_TOTAL>>>(tmA, tmB);
    // 3) finalize: full A rows (zeros + sparse) + C rows
    finalize_kernel<<<NROWS, 256>>>(Lm, Cout, Aout);
}

// round 14
// speedup vs baseline: 1.6689x; 1.6689x over previous
#include <cuda_runtime.h>
#include <cuda.h>
#include <cuda_bf16.h>
#include <cstdint>
#include <cstddef>

#define NROWS 32768
#define KDIM  4096
#define RDIM  256

// ---------------- static device scratch (no allocs allowed) ----------------
__device__ __nv_bfloat16 g_Asp[(size_t)NROWS * 512];   // [m][0:256]=hi(H), [256:512]=lo(H), 32MB
__device__ __nv_bfloat16 g_Bsp[(size_t)KDIM * 512];    // [k][0:256]=hi(Qt), [256:512]=lo(Qt), 4MB

// =========================================================================================
// PTX helpers
// =========================================================================================
__device__ __forceinline__ uint32_t smem_u32(const void* p) {
    uint32_t a;
    asm("{ .reg .u64 t; cvta.to.shared.u64 t, %1; cvt.u32.u64 %0, t; }" : "=r"(a) : "l"(p));
    return a;
}

#define MBARRIER_INIT(addr, cnt) \
    asm volatile("mbarrier.init.shared.b64 [%0], %1;" :: "r"((uint32_t)(addr)), "r"((uint32_t)(cnt)) : "memory")

#define MBARRIER_EXPECT_TX(addr, bytes) \
    asm volatile("mbarrier.arrive.expect_tx.shared.b64 _, [%0], %1;" :: "r"((uint32_t)(addr)), "r"((uint32_t)(bytes)) : "memory")

#define MBARRIER_WAIT_PARITY(addr, ph) do {                                             \
    uint32_t _m = (uint32_t)(addr); uint32_t _p = (uint32_t)(ph); uint32_t _d;          \
    asm volatile("{ .reg .pred p; mbarrier.try_wait.parity.acquire.cta.shared::cta.b64 p, [%1], %2; selp.b32 %0, 1, 0, p; }" \
                 : "=r"(_d) : "r"(_m), "r"(_p) : "memory");                             \
    if (!_d) {                                                                          \
        asm volatile("{ .reg .pred P1; WL_%=: mbarrier.try_wait.parity.acquire.cta.shared::cta.b64 P1, [%0], %1, 0x989680; " \
                     "@P1 bra.uni WD_%=; bra.uni WL_%=; WD_%=: }"                       \
                     :: "r"(_m), "r"(_p) : "memory");                                   \
    }                                                                                   \
} while (0)

__device__ __forceinline__ void tma2d(uint32_t dst, const CUtensorMap* m, int x, int y, uint32_t mbar) {
    asm volatile("cp.async.bulk.tensor.2d.shared::cta.global.tile.mbarrier::complete_tx::bytes "
                 "[%0], [%1, {%2, %3}], [%4];"
                 :: "r"(dst), "l"(m), "r"(x), "r"(y), "r"(mbar) : "memory");
}

// SMEM descriptor, K-major SW128 (layout=2, version=1, SBO=64, LBO=1)
static constexpr uint64_t SMEM_DESC_BASE_SW128 =
    (uint64_t(2) << 61) | (uint64_t(1) << 46) | (uint64_t(64) << 32) | (uint64_t(1) << 16);
#define MAKE_SMEM_DESC(a) (SMEM_DESC_BASE_SW128 | ((uint64_t)((a) >> 4) & 0x3FFF))

#define MMA_BF16(d, ad, bd, en)                                                        \
    asm volatile(                                                                      \
        "{ .reg .pred p; setp.ne.u32 p, %4, 0;"                                        \
        "tcgen05.mma.cta_group::1.kind::f16 [%0], %1, %2, %3, {%5, %5, %5, %5}, p; }"  \
        :: "r"(d), "l"(ad), "l"(bd), "r"(GM_IDESC), "r"(en), "r"(0u) : "memory")

// =========================================================================================
// tcgen05 GEMM, flat, 256(m) x 256(n) CTA tile, DEDUPLICATED split-term loads:
// per 64-col chunk, stage pair (Ah,Bh) then (Al,Bl); issue T1=Ah·Bh, T2=Ah·Bl, T3=Al·Bh
// from the two resident stages. 8 stage-loads instead of 12 (ops traffic -33%).
// Epilogue: plain logits store (R9-validated).
// =========================================================================================
#define GM_STAGES 3
#define GM_NLD    8        // 4 chunks x 2 stages
#define GM_ABYTES 32768    // 256 x 64 bf16
#define GM_BBYTES 32768
#define SM_OFF_TMEM     0
#define SM_OFF_FULL(s)  (8 + (s) * 8)
#define SM_OFF_MDONE(s) (40 + (s) * 8)
#define SM_OFF_FINAL    72
#define SM_OFF_A(s)     (1024 + (s) * 65536)
#define SM_OFF_B(s)     (1024 + (s) * 65536 + 32768)
#define GM_SMEM_TOTAL   (1024 + 3 * 65536)   // 197632

// idesc: F32 accum, BF16 a/b, M=128 (bits[24:29)=M/16), N=256 (bits[17:23)=N/8)
#define GM_IDESC ((1u << 4) | (1u << 7) | (1u << 10) | ((256u / 8) << 17) | ((128u / 16) << 24))

__global__ __launch_bounds__(128) void gemm_tc(const __grid_constant__ CUtensorMap tmA,
                                               const __grid_constant__ CUtensorMap tmB,
                                               float* __restrict__ out) {
#if defined(__CUDA_ARCH_FEAT_SM103_ALL) || defined(__CUDA_ARCH_FEAT_SM100_ALL)
    extern __shared__ char smem[];
    const uint32_t sb = smem_u32(smem);
    const int tid = threadIdx.x;
    const int wid = tid >> 5;
    const int lid = tid & 31;
    const int m0 = blockIdx.y * 256;
    const int n0 = blockIdx.x * 256;

    if (wid == 0)
        asm volatile("tcgen05.alloc.cta_group::1.sync.aligned.shared::cta.b32 [%0], %1;"
                     :: "r"(sb + SM_OFF_TMEM), "r"(512u) : "memory");
    if (tid == 0) {
        for (int s = 0; s < GM_STAGES; s++) {
            MBARRIER_INIT(sb + SM_OFF_FULL(s), 1);
            MBARRIER_INIT(sb + SM_OFF_MDONE(s), 1);
        }
        MBARRIER_INIT(sb + SM_OFF_FINAL, 1);
    }
    __syncthreads();

    uint32_t tmem;
    asm volatile("ld.shared.b32 %0, [%1];" : "=r"(tmem) : "r"(sb + SM_OFF_TMEM));

    if (tid == 0) {
        // producer: 8 stage-loads; even i -> (Ah,Bh) of chunk i/2, odd i -> (Al,Bl)
        int phase[GM_STAGES] = {0, 0, 0};
#pragma unroll 1
        for (int i = 0; i < GM_NLD; i++) {
            int s = i % GM_STAGES;
            if (i >= GM_STAGES) {
                MBARRIER_WAIT_PARITY(sb + SM_OFF_MDONE(s), phase[s]);
                phase[s] ^= 1;
            }
            MBARRIER_EXPECT_TX(sb + SM_OFF_FULL(s), GM_ABYTES + GM_BBYTES);
            int kk = (i >> 1) * 64;
            int x  = (i & 1) ? 256 + kk : kk;       // hi cols [0:256), lo cols [256:512)
            tma2d(sb + SM_OFF_A(s), &tmA, x, m0, sb + SM_OFF_FULL(s));
            tma2d(sb + SM_OFF_B(s), &tmB, x, n0, sb + SM_OFF_FULL(s));
        }
    } else if (tid == 32) {
        // MMA issuer: per chunk, stages s0=(Ah,Bh), s1=(Al,Bl); T1,T2,T3 cross-products
        int phase[GM_STAGES] = {0, 0, 0};
#pragma unroll 1
        for (int c = 0; c < 4; c++) {
            int s0 = (2 * c) % GM_STAGES;
            int s1 = (2 * c + 1) % GM_STAGES;

            MBARRIER_WAIT_PARITY(sb + SM_OFF_FULL(s0), phase[s0]);
            phase[s0] ^= 1;
            uint64_t a0h = MAKE_SMEM_DESC(sb + SM_OFF_A(s0));           // Ah slab0
            uint64_t a1h = MAKE_SMEM_DESC(sb + SM_OFF_A(s0) + 16384);   // Ah slab1
            uint64_t bh  = MAKE_SMEM_DESC(sb + SM_OFF_B(s0));           // Bh
            // T1 = Ah · Bh
#pragma unroll
            for (int k = 0; k < 4; k++) {
                uint32_t en = (c > 0 || k > 0) ? 1u : 0u;
                MMA_BF16(tmem,       a0h + k * 2, bh + k * 2, en);
                MMA_BF16(tmem + 256, a1h + k * 2, bh + k * 2, en);
            }

            MBARRIER_WAIT_PARITY(sb + SM_OFF_FULL(s1), phase[s1]);
            phase[s1] ^= 1;
            uint64_t a0l = MAKE_SMEM_DESC(sb + SM_OFF_A(s1));           // Al slab0
            uint64_t a1l = MAKE_SMEM_DESC(sb + SM_OFF_A(s1) + 16384);   // Al slab1
            uint64_t bl  = MAKE_SMEM_DESC(sb + SM_OFF_B(s1));           // Bl
            // T2 = Ah · Bl ; T3 = Al · Bh
#pragma unroll
            for (int k = 0; k < 4; k++) {
                MMA_BF16(tmem,       a0h + k * 2, bl + k * 2, 1u);
                MMA_BF16(tmem + 256, a1h + k * 2, bl + k * 2, 1u);
                MMA_BF16(tmem,       a0l + k * 2, bh + k * 2, 1u);
                MMA_BF16(tmem + 256, a1l + k * 2, bh + k * 2, 1u);
            }
            // both stages fully consumed after T3
            asm volatile("tcgen05.commit.cta_group::1.mbarrier::arrive::one.shared::cluster.b64 [%0];"
                         :: "r"(sb + SM_OFF_MDONE(s0)) : "memory");
            asm volatile("tcgen05.commit.cta_group::1.mbarrier::arrive::one.shared::cluster.b64 [%0];"
                         :: "r"(sb + SM_OFF_MDONE(s1)) : "memory");
        }
        asm volatile("tcgen05.commit.cta_group::1.mbarrier::arrive::one.shared::cluster.b64 [%0];"
                     :: "r"(sb + SM_OFF_FINAL) : "memory");
    }

    // everyone: wait for all MMAs, then epilogue (two slabs, plain logits store)
    MBARRIER_WAIT_PARITY(sb + SM_OFF_FINAL, 0);
    asm volatile("tcgen05.fence::after_thread_sync;" ::: "memory");

#pragma unroll 1
    for (int slab = 0; slab < 2; slab++) {
        const int row = m0 + slab * 128 + wid * 32 + lid;
        float* orow = out + (size_t)row * KDIM + n0;
        const uint32_t tbase = tmem + slab * 256;
#pragma unroll 1
        for (int c = 0; c < 8; c++) {
            uint32_t r[32];
            asm volatile(
                "tcgen05.ld.sync.aligned.32x32b.x32.b32 "
                "{%0, %1, %2, %3, %4, %5, %6, %7, %8, %9, %10, %11, %12, %13, %14, %15, "
                " %16, %17, %18, %19, %20, %21, %22, %23, %24, %25, %26, %27, %28, %29, %30, %31}, [%32];"
                : "=r"(r[0]),  "=r"(r[1]),  "=r"(r[2]),  "=r"(r[3]),
                  "=r"(r[4]),  "=r"(r[5]),  "=r"(r[6]),  "=r"(r[7]),
                  "=r"(r[8]),  "=r"(r[9]),  "=r"(r[10]), "=r"(r[11]),
                  "=r"(r[12]), "=r"(r[13]), "=r"(r[14]), "=r"(r[15]),
                  "=r"(r[16]), "=r"(r[17]), "=r"(r[18]), "=r"(r[19]),
                  "=r"(r[20]), "=r"(r[21]), "=r"(r[22]), "=r"(r[23]),
                  "=r"(r[24]), "=r"(r[25]), "=r"(r[26]), "=r"(r[27]),
                  "=r"(r[28]), "=r"(r[29]), "=r"(r[30]), "=r"(r[31])
                : "r"(tbase + c * 32));
            asm volatile("tcgen05.wait::ld.sync.aligned;" ::: "memory");
            float4* dst = (float4*)(orow + c * 32);
#pragma unroll
            for (int j = 0; j < 8; j++)
                dst[j] = make_float4(__uint_as_float(r[4 * j]),     __uint_as_float(r[4 * j + 1]),
                                     __uint_as_float(r[4 * j + 2]), __uint_as_float(r[4 * j + 3]));
        }
    }
    asm volatile("tcgen05.fence::before_thread_sync;" ::: "memory");
    __syncthreads();
    if (wid == 0) {
        asm volatile("tcgen05.relinquish_alloc_permit.cta_group::1.sync.aligned;");
        asm volatile("tcgen05.dealloc.cta_group::1.sync.aligned.b32 %0, %1;" :: "r"(tmem), "r"(512u));
    }
#endif  // arch guard
}

// =========================================================================================
// Fused prologue (R9-validated): y<32 -> Qt GEMM tile w/ split epilogue; y>=32 -> H split
// =========================================================================================
__device__ __forceinline__ unsigned long long pk2(float lo, float hi) {
    unsigned long long r;
    asm("mov.b64 %0, {%1, %2};" : "=l"(r) : "r"(__float_as_uint(lo)), "r"(__float_as_uint(hi)));
    return r;
}
__device__ __forceinline__ void fma2(unsigned long long &d, unsigned long long a, unsigned long long b) {
    asm("fma.rn.f32x2 %0, %1, %2, %3;" : "=l"(d) : "l"(a), "l"(b), "l"(d));
}
__device__ __forceinline__ float2 upk(unsigned long long v) {
    unsigned lo, hi;
    asm("mov.b64 {%0, %1}, %2;" : "=r"(lo), "=r"(hi) : "l"(v));
    float2 f; f.x = __uint_as_float(lo); f.y = __uint_as_float(hi);
    return f;
}

#define SPLIT_YBASE 32

__global__ __launch_bounds__(256) void prologue_kernel(const float* __restrict__ H,
                                                       const float* __restrict__ Lmat,
                                                       const float* __restrict__ W,
                                                       __nv_bfloat16* __restrict__ Asp,
                                                       __nv_bfloat16* __restrict__ Bsp) {
    __shared__ float As[32][132];
    __shared__ float Bs[32][132];
    const int tid = threadIdx.x;

    if (blockIdx.y >= SPLIT_YBASE) {
        int sbid = (blockIdx.y - SPLIT_YBASE) * 2 + blockIdx.x;
        int f = sbid * 256 + tid;
        int m = f >> 6;
        int r = (f & 63) << 2;
        float4 x = ((const float4*)H)[f];
        __nv_bfloat16 h0 = __float2bfloat16(x.x), h1 = __float2bfloat16(x.y);
        __nv_bfloat16 h2 = __float2bfloat16(x.z), h3 = __float2bfloat16(x.w);
        __nv_bfloat162 hiA(h0, h1), hiB(h2, h3);
        __nv_bfloat162 loA(__float2bfloat16(x.x - __bfloat162float(h0)),
                           __float2bfloat16(x.y - __bfloat162float(h1)));
        __nv_bfloat162 loB(__float2bfloat16(x.z - __bfloat162float(h2)),
                           __float2bfloat16(x.w - __bfloat162float(h3)));
        __nv_bfloat162* dh = (__nv_bfloat162*)(Asp + (size_t)m * 512 + r);
        __nv_bfloat162* dl = (__nv_bfloat162*)(Asp + (size_t)m * 512 + 256 + r);
        dh[0] = hiA; dh[1] = hiB;
        dl[0] = loA; dl[1] = loB;
        return;
    }

    const int K = RDIM;
    const int tx = tid & 15;
    const int ty = tid >> 4;
    const int bm = blockIdx.y * 128;
    const int bn = blockIdx.x * 128;
    const int lrow = tid >> 3;
    const int lcol = (tid & 7) << 2;

    unsigned long long acc[8][4];
#pragma unroll
    for (int i = 0; i < 8; i++)
#pragma unroll
        for (int j = 0; j < 4; j++) acc[i][j] = 0ull;

    for (int kk = 0; kk < K; kk += 32) {
#pragma unroll
        for (int p = 0; p < 4; p++) {
            int r = lrow + p * 32;
            float4 av = *(const float4*)(Lmat + (size_t)(bm + r) * K + kk + lcol);
            As[lcol + 0][r] = av.x; As[lcol + 1][r] = av.y;
            As[lcol + 2][r] = av.z; As[lcol + 3][r] = av.w;
            float4 bv = *(const float4*)(W + (size_t)(bn + r) * K + kk + lcol);
            Bs[lcol + 0][r] = bv.x; Bs[lcol + 1][r] = bv.y;
            Bs[lcol + 2][r] = bv.z; Bs[lcol + 3][r] = bv.w;
        }
        __syncthreads();
#pragma unroll
        for (int k2 = 0; k2 < 32; k2++) {
            float4 a0 = *(const float4*)&As[k2][ty * 8];
            float4 a1 = *(const float4*)&As[k2][ty * 8 + 4];
            float4 b0 = *(const float4*)&Bs[k2][tx * 8];
            float4 b1 = *(const float4*)&Bs[k2][tx * 8 + 4];
            unsigned long long av[8];
            av[0] = pk2(a0.x, a0.x); av[1] = pk2(a0.y, a0.y);
            av[2] = pk2(a0.z, a0.z); av[3] = pk2(a0.w, a0.w);
            av[4] = pk2(a1.x, a1.x); av[5] = pk2(a1.y, a1.y);
            av[6] = pk2(a1.z, a1.z); av[7] = pk2(a1.w, a1.w);
            unsigned long long bv2[4];
            bv2[0] = pk2(b0.x, b0.y); bv2[1] = pk2(b0.z, b0.w);
            bv2[2] = pk2(b1.x, b1.y); bv2[3] = pk2(b1.z, b1.w);
#pragma unroll
            for (int i = 0; i < 8; i++)
#pragma unroll
                for (int j = 0; j < 4; j++) fma2(acc[i][j], av[i], bv2[j]);
        }
        __syncthreads();
    }

#pragma unroll
    for (int i = 0; i < 8; i++) {
        float2 c0 = upk(acc[i][0]), c1 = upk(acc[i][1]);
        float2 c2 = upk(acc[i][2]), c3 = upk(acc[i][3]);
        float v[8] = {c0.x, c0.y, c1.x, c1.y, c2.x, c2.y, c3.x, c3.y};
        int krow = bm + ty * 8 + i;
        int cbase = bn + tx * 8;
        __nv_bfloat162 hi[4], lo[4];
#pragma unroll
        for (int j = 0; j < 4; j++) {
            __nv_bfloat16 h0 = __float2bfloat16(v[2 * j]);
            __nv_bfloat16 h1 = __float2bfloat16(v[2 * j + 1]);
            hi[j] = __nv_bfloat162(h0, h1);
            lo[j] = __nv_bfloat162(__float2bfloat16(v[2 * j] - __bfloat162float(h0)),
                                   __float2bfloat16(v[2 * j + 1] - __bfloat162float(h1)));
        }
        __nv_bfloat162* dh = (__nv_bfloat162*)(Bsp + (size_t)krow * 512 + cbase);
        __nv_bfloat162* dl = (__nv_bfloat162*)(Bsp + (size_t)krow * 512 + 256 + cbase);
#pragma unroll
        for (int j = 0; j < 4; j++) { dh[j] = hi[j]; dl[j] = lo[j]; }
    }
}

// =========================================================================================
// K3: register-resident row softmax (in place) + sparse C = A @ L  (R9-validated)
// =========================================================================================
__device__ __forceinline__ float warpMax(float v) {
#pragma unroll
    for (int o = 16; o > 0; o >>= 1) v = fmaxf(v, __shfl_xor_sync(0xffffffffu, v, o));
    return v;
}
__device__ __forceinline__ float warpSum(float v) {
#pragma unroll
    for (int o = 16; o > 0; o >>= 1) v += __shfl_xor_sync(0xffffffffu, v, o);
    return v;
}

__global__ __launch_bounds__(256) void softmax_c_kernel(float* __restrict__ Aout,
                                                        const float* __restrict__ Lmat,
                                                        float* __restrict__ Cout) {
    const int n = blockIdx.x;
    float4* rv = (float4*)(Aout + (size_t)n * KDIM);
    __shared__ float red[8];
    __shared__ float cacc[RDIM];
    __shared__ int   lidx[1024];
    __shared__ float lval[1024];
    __shared__ int   cnt;
    const int t = threadIdx.x;

    cacc[t] = 0.0f;
    if (t == 0) cnt = 0;

    float4 v[4];
    float lmax = -3.4e38f;
#pragma unroll
    for (int i = 0; i < 4; i++) {
        v[i] = rv[i * 256 + t];
        lmax = fmaxf(lmax, fmaxf(fmaxf(v[i].x, v[i].y), fmaxf(v[i].z, v[i].w)));
    }
    lmax = warpMax(lmax);
    if ((t & 31) == 0) red[t >> 5] = lmax;
    __syncthreads();
    float m = red[0];
#pragma unroll
    for (int w = 1; w < 8; w++) m = fmaxf(m, red[w]);

    float lsum = 0.0f;
#pragma unroll
    for (int i = 0; i < 4; i++) {
        float4 e;
        e.x = __expf(v[i].x - m);
        e.y = __expf(v[i].y - m);
        e.z = __expf(v[i].z - m);
        e.w = __expf(v[i].w - m);
        lsum += (e.x + e.y) + (e.z + e.w);
        int kbase = (i * 256 + t) * 4;
        float emx = fmaxf(fmaxf(e.x, e.y), fmaxf(e.z, e.w));
        if (emx > 1e-13f) {
            float ev[4] = {e.x, e.y, e.z, e.w};
#pragma unroll
            for (int c = 0; c < 4; c++) {
                if (ev[c] > 1e-13f) {
                    int p = atomicAdd(&cnt, 1);
                    if (p < 1024) { lidx[p] = kbase + c; lval[p] = ev[c]; }
                    else {
                        for (int r = 0; r < RDIM; r++)
                            atomicAdd(&cacc[r], ev[c] * Lmat[(size_t)(kbase + c) * RDIM + r]);
                    }
                }
            }
        }
        v[i] = e;
    }
    __syncthreads();
    lsum = warpSum(lsum);
    if ((t & 31) == 0) red[t >> 5] = lsum;
    __syncthreads();
    float s = 0.0f;
#pragma unroll
    for (int w = 0; w < 8; w++) s += red[w];
    const float inv = 1.0f / s;

#pragma unroll
    for (int i = 0; i < 4; i++) {
        float4 w = v[i];
        w.x *= inv; w.y *= inv; w.z *= inv; w.w *= inv;
        rv[i * 256 + t] = w;
    }

    int c_n = min(cnt, 1024);
    float c = cacc[t];
    for (int j = 0; j < c_n; j++)
        c += lval[j] * Lmat[(size_t)lidx[j] * RDIM + t];
    Cout[(size_t)n * RDIM + t] = c * inv;
}

// =========================================================================================
// host
// =========================================================================================
typedef CUresult (*PFN_encodeTiled)(CUtensorMap*, CUtensorMapDataType, cuuint32_t, void*,
                                    const cuuint64_t*, const cuuint64_t*, const cuuint32_t*,
                                    const cuuint32_t*, CUtensorMapInterleave, CUtensorMapSwizzle,
                                    CUtensorMapL2promotion, CUtensorMapFloatOOBfill);

static void encode_map(PFN_encodeTiled enc, CUtensorMap* tm, void* ptr,
                       uint64_t rows, uint32_t box_rows) {
    cuuint64_t dims[2]    = {512, rows};
    cuuint64_t strides[1] = {512 * sizeof(__nv_bfloat16)};
    cuuint32_t box[2]     = {64, box_rows};
    cuuint32_t es[2]      = {1, 1};
    enc(tm, CU_TENSOR_MAP_DATA_TYPE_BFLOAT16, 2, ptr, dims, strides, box, es,
        CU_TENSOR_MAP_INTERLEAVE_NONE, CU_TENSOR_MAP_SWIZZLE_128B,
        CU_TENSOR_MAP_L2_PROMOTION_L2_128B, CU_TENSOR_MAP_FLOAT_OOB_FILL_NONE);
}

extern "C" void kernel_launch(void* const* d_in, const int* in_sizes, int n_in,
                              void* d_out, int out_size) {
    (void)in_sizes; (void)n_in; (void)out_size;
    const float* H  = (const float*)d_in[0];   // 32768 x 256
    const float* Lm = (const float*)d_in[1];   // 4096 x 256
    const float* W  = (const float*)d_in[2];   // 256 x 256
    float* Cout = (float*)d_out;
    float* Aout = Cout + (size_t)NROWS * RDIM;

    __nv_bfloat16* Asp; __nv_bfloat16* Bsp;
    cudaGetSymbolAddress((void**)&Asp, g_Asp);
    cudaGetSymbolAddress((void**)&Bsp, g_Bsp);

    static PFN_encodeTiled enc = nullptr;
    if (!enc) {
        void* fn = nullptr;
        cudaDriverEntryPointQueryResult qr;
        cudaGetDriverEntryPoint("cuTensorMapEncodeTiled", &fn, cudaEnableDefault, &qr);
        enc = (PFN_encodeTiled)fn;
    }

    CUtensorMap tmA, tmB;
    encode_map(enc, &tmA, Asp, NROWS, 256);
    encode_map(enc, &tmB, Bsp, KDIM, 256);

    static bool attr_set = false;
    if (!attr_set) {
        cudaFuncSetAttribute(gemm_tc, cudaFuncAttributeMaxDynamicSharedMemorySize, GM_SMEM_TOTAL);
        attr_set = true;
    }

    // 1) fused prologue
    prologue_kernel<<<dim3(2, SPLIT_YBASE + 4096), 256>>>(H, Lm, W, Asp, Bsp);
    // 2) logits = dedup 3-term bf16 tcgen05 GEMM (256x256 tile) -> A region of d_out
    gemm_tc<<<dim3(KDIM / 256, NROWS / 256), 128, GM_SMEM_TOTAL>>>(tmA, tmB, Aout);
    // 3) register-row softmax + sparse C
    softmax_c_kernel<<<NROWS, 256>>>(Aout, Lm, Cout);
}